// round 3
// baseline (speedup 1.0000x reference)
#include <cuda_runtime.h>
#include <cstdint>

#define DEVI __device__ __forceinline__

// ---- problem constants ----
#define NB 4
#define NL 2048
#define ND 512
#define NH 8
#define HD 64
#define NBH (NB*NH)

// ---- scratch (static device globals: the sanctioned scratch mechanism) ----
static __device__ float g_q[(size_t)NB * NH * NL * HD];
static __device__ float g_k[(size_t)NB * NH * NL * HD];
static __device__ float g_v[(size_t)NB * NH * NL * HD];
static __device__ float g_ctx[(size_t)NB * NL * ND];
static __device__ float g_final[(size_t)NB * NL * ND];
static __device__ float g_attn[(size_t)NB * NH * NL * NL];   // fallback if attn not in d_out

// ---- small PTX helpers ----
DEVI uint32_t f2tf(float f) {
    uint32_t u;
    asm volatile("cvt.rna.tf32.f32 %0, %1;" : "=r"(u) : "f"(f));
    return u;
}

DEVI void mma_tf32(float c[4], const uint32_t a[4], const uint32_t b[2]) {
    asm volatile(
        "mma.sync.aligned.m16n8k8.row.col.f32.tf32.tf32.f32 "
        "{%0,%1,%2,%3},{%4,%5,%6,%7},{%8,%9},{%0,%1,%2,%3};"
        : "+f"(c[0]), "+f"(c[1]), "+f"(c[2]), "+f"(c[3])
        : "r"(a[0]), "r"(a[1]), "r"(a[2]), "r"(a[3]), "r"(b[0]), "r"(b[1]));
}

DEVI void cpa16(float* s, const float* g) {
    uint32_t sa = (uint32_t)__cvta_generic_to_shared(s);
    asm volatile("cp.async.cg.shared.global [%0], [%1], 16;" :: "r"(sa), "l"(g));
}
DEVI void cp_commit() { asm volatile("cp.async.commit_group;"); }
template <int N> DEVI void cp_wait() { asm volatile("cp.async.wait_group %0;" :: "n"(N)); }

// ============================================================================
// TN GEMM: out[m,n] = sum_k A[m,k] * W[n,k] + bias[n]
//   M = NB*NL = 8192, N = 512, K = 512.
//   PERM=1: write out as [B, H, L, 64] head-split layout (QKV projections).
//   PERM=0: write out as [M, 512] row-major (output projection / context).
// BM=128, BN=128, BK=32, 256 threads (8 warps, warp tile 32x64), TF32 mma.
// smem layout: As/Bs [2][128][36] (pad 4 -> stride%32==4, conflict-free frags)
// ============================================================================
template <int PERM>
__global__ __launch_bounds__(256, 1) void gemm_tn(
    const float* __restrict__ A, const float* __restrict__ W,
    const float* __restrict__ bias, float* __restrict__ out)
{
    extern __shared__ float sm[];
    float* As = sm;                  // [2][128][36]
    float* Bs = sm + 2 * 128 * 36;   // [2][128][36]
    const int tid  = threadIdx.x;
    const int lane = tid & 31, wid = tid >> 5;
    const int wm = wid & 3, wn = wid >> 2;
    const int m0 = blockIdx.x * 128, n0 = blockIdx.y * 128;

    float acc[2][8][4];
#pragma unroll
    for (int i = 0; i < 2; i++)
#pragma unroll
        for (int j = 0; j < 8; j++)
#pragma unroll
            for (int e = 0; e < 4; e++) acc[i][j][e] = 0.f;

    const int lr = tid >> 3, lc = (tid & 7) * 4;

    auto load_tile = [&](int buf, int kt) {
        const float* ag = A + (size_t)m0 * 512 + kt * 32;
        const float* bg = W + (size_t)n0 * 512 + kt * 32;
#pragma unroll
        for (int i = 0; i < 4; i++) {
            int r = lr + 32 * i;
            cpa16(&As[buf * 4608 + r * 36 + lc], ag + (size_t)r * 512 + lc);
            cpa16(&Bs[buf * 4608 + r * 36 + lc], bg + (size_t)r * 512 + lc);
        }
        cp_commit();
    };

    load_tile(0, 0);
    for (int kt = 0; kt < 16; kt++) {
        if (kt < 15) { load_tile((kt + 1) & 1, kt + 1); cp_wait<1>(); }
        else         { cp_wait<0>(); }
        __syncthreads();
        const float* as = &As[(kt & 1) * 4608];
        const float* bs = &Bs[(kt & 1) * 4608];
#pragma unroll
        for (int kk = 0; kk < 4; kk++) {
            int k0 = kk * 8 + (lane & 3);
            uint32_t af[2][4], bf[8][2];
#pragma unroll
            for (int i = 0; i < 2; i++) {
                int m = wm * 32 + i * 16 + (lane >> 2);
                af[i][0] = f2tf(as[m * 36 + k0]);
                af[i][1] = f2tf(as[(m + 8) * 36 + k0]);
                af[i][2] = f2tf(as[m * 36 + k0 + 4]);
                af[i][3] = f2tf(as[(m + 8) * 36 + k0 + 4]);
            }
#pragma unroll
            for (int j = 0; j < 8; j++) {
                int n = wn * 64 + j * 8 + (lane >> 2);
                bf[j][0] = f2tf(bs[n * 36 + k0]);
                bf[j][1] = f2tf(bs[n * 36 + k0 + 4]);
            }
#pragma unroll
            for (int i = 0; i < 2; i++)
#pragma unroll
                for (int j = 0; j < 8; j++) mma_tf32(acc[i][j], af[i], bf[j]);
        }
        __syncthreads();
    }

#pragma unroll
    for (int i = 0; i < 2; i++)
#pragma unroll
        for (int j = 0; j < 8; j++)
#pragma unroll
            for (int e = 0; e < 4; e++) {
                int row = m0 + wm * 32 + i * 16 + (lane >> 2) + ((e >> 1) * 8);
                int col = n0 + wn * 64 + j * 8 + ((lane & 3) * 2) + (e & 1);
                float v = acc[i][j][e] + __ldg(&bias[col]);
                if (PERM) {
                    int bb = row >> 11, l = row & (NL - 1);
                    out[(((size_t)(bb * NH + (col >> 6))) * NL + l) * HD + (col & 63)] = v;
                } else {
                    out[(size_t)row * ND + col] = v;
                }
            }
}

// ============================================================================
// Scores + softmax: per CTA 16 q rows x full L keys kept in smem.
//   S = Q K^T (TF32 mma), then s = S*0.125 - 1e30*mask, row softmax, attn write.
// grid = (L/16, B*H), 256 threads.
// smem: Ssm [16][2052] + Ks [2][128][68] + Qs [16][68]  = 205,312 B
// ============================================================================
__global__ __launch_bounds__(256, 1) void scores_softmax(
    const float* __restrict__ Q, const float* __restrict__ K,
    const int* __restrict__ mask, float* __restrict__ attn)
{
    extern __shared__ float sm[];
    float* Ssm = sm;                   // [16][2052]
    float* Ks  = sm + 16 * 2052;       // [2][128][68]
    float* Qs  = Ks + 2 * 128 * 68;    // [16][68]
    const int tid = threadIdx.x, lane = tid & 31, wid = tid >> 5;
    const int bh = blockIdx.y, q0 = blockIdx.x * 16;

    const float* Qg = Q + ((size_t)bh * NL + q0) * HD;
    const float* Kg = K + (size_t)bh * NL * HD;

    {   // Q tile: 16 x 64, one float4 per thread (goes into cp.async group 0)
        int r = tid >> 4, c = (tid & 15) * 4;
        cpa16(&Qs[r * 68 + c], Qg + r * HD + c);
    }
    auto loadK = [&](int buf, int kt) {
#pragma unroll
        for (int i = 0; i < 8; i++) {
            int r = (tid >> 4) + 16 * i, c = (tid & 15) * 4;
            cpa16(&Ks[buf * 8704 + r * 68 + c], Kg + (size_t)(kt * 128 + r) * HD + c);
        }
        cp_commit();
    };
    loadK(0, 0);

    for (int kt = 0; kt < 16; kt++) {
        if (kt < 15) { loadK((kt + 1) & 1, kt + 1); cp_wait<1>(); }
        else         { cp_wait<0>(); }
        __syncthreads();
        const float* ks = &Ks[(kt & 1) * 8704];
        const int tw = wid * 16;            // 16 tokens per warp
        float acc[2][4] = {};
#pragma unroll
        for (int kk = 0; kk < 8; kk++) {
            int k0 = kk * 8 + (lane & 3);
            uint32_t af[4], bf[2][2];
            int r = lane >> 2;
            af[0] = f2tf(Qs[r * 68 + k0]);
            af[1] = f2tf(Qs[(r + 8) * 68 + k0]);
            af[2] = f2tf(Qs[r * 68 + k0 + 4]);
            af[3] = f2tf(Qs[(r + 8) * 68 + k0 + 4]);
#pragma unroll
            for (int j = 0; j < 2; j++) {
                int n = tw + j * 8 + (lane >> 2);
                bf[j][0] = f2tf(ks[n * 68 + k0]);
                bf[j][1] = f2tf(ks[n * 68 + k0 + 4]);
            }
            mma_tf32(acc[0], af, bf[0]);
            mma_tf32(acc[1], af, bf[1]);
        }
#pragma unroll
        for (int j = 0; j < 2; j++)
#pragma unroll
            for (int e = 0; e < 4; e++) {
                int r   = (lane >> 2) + ((e >> 1) * 8);
                int col = kt * 128 + tw + j * 8 + (lane & 3) * 2 + (e & 1);
                Ssm[r * 2052 + col] = acc[j][e];
            }
        __syncthreads();
    }

    // masked softmax, one warp handles 2 rows
    const int b = bh >> 3;
#pragma unroll
    for (int rr = 0; rr < 2; rr++) {
        int r = wid * 2 + rr;
        float* srow = &Ssm[r * 2052];
        const int* mrow = mask + ((size_t)b * NL + q0 + r) * NL;
        float mx = -3.4e38f;
        for (int i = lane; i < NL; i += 32) {
            float s = fmaf((float)mrow[i], -1e30f, srow[i] * 0.125f);
            srow[i] = s;
            mx = fmaxf(mx, s);
        }
#pragma unroll
        for (int o = 16; o > 0; o >>= 1) mx = fmaxf(mx, __shfl_xor_sync(0xffffffffu, mx, o));
        float l = 0.f;
        for (int i = lane; i < NL; i += 32) {
            float p = __expf(srow[i] - mx);
            srow[i] = p;
            l += p;
        }
#pragma unroll
        for (int o = 16; o > 0; o >>= 1) l += __shfl_xor_sync(0xffffffffu, l, o);
        float inv = 1.f / l;
        float* arow = attn + ((size_t)bh * NL + q0 + r) * NL;
        for (int i = lane; i < NL; i += 32) arow[i] = srow[i] * inv;
    }
}

// ============================================================================
// P·V: per (b,h), ctx[b,l,h*64+d] = sum_t attn[bh,l,t] * V[bh,t,d]
//   M=2048, N=64, K=2048. BM=128, BN=64, BK=32, 256 threads (warp tile 32x32).
// smem: As [2][128][36] + Vs [2][32][68] = 54,272 B
// ============================================================================
__global__ __launch_bounds__(256, 1) void pv_gemm(
    const float* __restrict__ attn, const float* __restrict__ V,
    float* __restrict__ ctx)
{
    extern __shared__ float sm[];
    float* As = sm;                  // [2][128][36]
    float* Vs = sm + 2 * 128 * 36;   // [2][32][68]
    const int tid = threadIdx.x, lane = tid & 31, wid = tid >> 5;
    const int wm = wid & 3, wn = wid >> 2;
    const int bh = blockIdx.y, m0 = blockIdx.x * 128;
    const int b = bh >> 3, h = bh & 7;
    const float* Ag = attn + (size_t)bh * NL * NL;
    const float* Vg = V + (size_t)bh * NL * HD;

    float acc[2][4][4];
#pragma unroll
    for (int i = 0; i < 2; i++)
#pragma unroll
        for (int j = 0; j < 4; j++)
#pragma unroll
            for (int e = 0; e < 4; e++) acc[i][j][e] = 0.f;

    auto load_tile = [&](int buf, int kt) {
#pragma unroll
        for (int i = 0; i < 4; i++) {
            int r = (tid >> 3) + 32 * i, c = (tid & 7) * 4;
            cpa16(&As[buf * 4608 + r * 36 + c], Ag + (size_t)(m0 + r) * NL + kt * 32 + c);
        }
#pragma unroll
        for (int i = 0; i < 2; i++) {
            int r = (tid >> 4) + 16 * i, c = (tid & 15) * 4;
            cpa16(&Vs[buf * 2176 + r * 68 + c], Vg + (size_t)(kt * 32 + r) * HD + c);
        }
        cp_commit();
    };

    load_tile(0, 0);
    for (int kt = 0; kt < 64; kt++) {
        if (kt < 63) { load_tile((kt + 1) & 1, kt + 1); cp_wait<1>(); }
        else         { cp_wait<0>(); }
        __syncthreads();
        const float* as = &As[(kt & 1) * 4608];
        const float* vs = &Vs[(kt & 1) * 2176];
#pragma unroll
        for (int kk = 0; kk < 4; kk++) {
            int k0 = kk * 8 + (lane & 3);
            uint32_t af[2][4], bf[4][2];
#pragma unroll
            for (int i = 0; i < 2; i++) {
                int m = wm * 32 + i * 16 + (lane >> 2);
                af[i][0] = f2tf(as[m * 36 + k0]);
                af[i][1] = f2tf(as[(m + 8) * 36 + k0]);
                af[i][2] = f2tf(as[m * 36 + k0 + 4]);
                af[i][3] = f2tf(as[(m + 8) * 36 + k0 + 4]);
            }
#pragma unroll
            for (int j = 0; j < 4; j++) {
                int n = wn * 32 + j * 8 + (lane >> 2);
                bf[j][0] = f2tf(vs[k0 * 68 + n]);
                bf[j][1] = f2tf(vs[(k0 + 4) * 68 + n]);
            }
#pragma unroll
            for (int i = 0; i < 2; i++)
#pragma unroll
                for (int j = 0; j < 4; j++) mma_tf32(acc[i][j], af[i], bf[j]);
        }
        __syncthreads();
    }

#pragma unroll
    for (int i = 0; i < 2; i++)
#pragma unroll
        for (int j = 0; j < 4; j++)
#pragma unroll
            for (int e = 0; e < 4; e++) {
                int l = m0 + wm * 32 + i * 16 + (lane >> 2) + ((e >> 1) * 8);
                int d = wn * 32 + j * 8 + (lane & 3) * 2 + (e & 1);
                ctx[((size_t)b * NL + l) * ND + h * HD + d] = acc[i][j][e];
            }
}

// ============================================================================
// launch
// ============================================================================
extern "C" void kernel_launch(void* const* d_in, const int* in_sizes, int n_in,
                              void* d_out, int out_size) {
    (void)in_sizes; (void)n_in;
    const float* x_q = (const float*)d_in[0];
    const float* x_k = (const float*)d_in[1];
    const float* x_v = (const float*)d_in[2];
    const int*   msk = (const int*)d_in[3];
    const float* Wq  = (const float*)d_in[4];
    const float* bq  = (const float*)d_in[5];
    const float* Wk  = (const float*)d_in[6];
    const float* bk  = (const float*)d_in[7];
    const float* Wv  = (const float*)d_in[8];
    const float* bv  = (const float*)d_in[9];
    const float* Wo  = (const float*)d_in[10];
    const float* bo  = (const float*)d_in[11];

    const long long FINAL_N = (long long)NB * NL * ND;              //   4,194,304
    const long long ATTN_N  = (long long)NB * NH * NL * NL;         // 134,217,728

    float* outp = (float*)d_out;
    float* finalp;
    float* attnp;
    if ((long long)out_size >= FINAL_N + ATTN_N) { finalp = outp; attnp = outp + FINAL_N; }
    else if ((long long)out_size == ATTN_N)      { attnp = outp;  finalp = g_final; }
    else                                         { finalp = outp; attnp = g_attn; }

    const int SM_GEMM   = 2 * (2 * 128 * 36) * 4;                   // 73,728 B
    const int SM_SCORES = (16 * 2052 + 2 * 128 * 68 + 16 * 68) * 4; // 205,312 B
    const int SM_PV     = (2 * 128 * 36 + 2 * 32 * 68) * 4;         // 54,272 B

    cudaFuncSetAttribute(gemm_tn<1>, cudaFuncAttributeMaxDynamicSharedMemorySize, SM_GEMM);
    cudaFuncSetAttribute(gemm_tn<0>, cudaFuncAttributeMaxDynamicSharedMemorySize, SM_GEMM);
    cudaFuncSetAttribute(scores_softmax, cudaFuncAttributeMaxDynamicSharedMemorySize, SM_SCORES);
    cudaFuncSetAttribute(pv_gemm, cudaFuncAttributeMaxDynamicSharedMemorySize, SM_PV);

    float* qg; cudaGetSymbolAddress((void**)&qg, g_q);
    float* kg; cudaGetSymbolAddress((void**)&kg, g_k);
    float* vg; cudaGetSymbolAddress((void**)&vg, g_v);
    float* cg; cudaGetSymbolAddress((void**)&cg, g_ctx);

    dim3 gp(64, 4);
    gemm_tn<1><<<gp, 256, SM_GEMM>>>(x_q, Wq, bq, qg);
    gemm_tn<1><<<gp, 256, SM_GEMM>>>(x_k, Wk, bk, kg);
    gemm_tn<1><<<gp, 256, SM_GEMM>>>(x_v, Wv, bv, vg);

    scores_softmax<<<dim3(NL / 16, NBH), 256, SM_SCORES>>>(qg, kg, msk, attnp);

    pv_gemm<<<dim3(NL / 128, NBH), 256, SM_PV>>>(attnp, vg, cg);

    gemm_tn<0><<<gp, 256, SM_GEMM>>>(cg, Wo, bo, finalp);
}